// round 15
// baseline (speedup 1.0000x reference)
#include <cuda_runtime.h>
#include <cuda_bf16.h>
#include <cstdint>
#include <cstddef>

#define H 384
#define W 384
#define BATCH 2
#define NWIN 48

#define H1SZ ((size_t)BATCH*H*W*64)   // elements per branch (bf16)
#define H2SZ ((size_t)BATCH*H*W*32)

// ---------------- scratch ----------------
__device__ __nv_bfloat16 g_h1[3*H1SZ];
__device__ __nv_bfloat16 g_h2[3*H2SZ];
__device__ __nv_bfloat16 g_feat[(size_t)BATCH*H*W*96];
__device__ __nv_bfloat16 g_aout[(size_t)BATCH*H*W*32];   // channel-last, shifted space
__device__ uint32_t g_bf1[3*1024];     // conv1 B frags (bf16x2, im2col K=32)
__device__ uint32_t g_bf2[3*9216];     // conv2 B frags
__device__ uint32_t g_bf3[3*4608];     // conv3 B frags
__device__ uint32_t g_bfo[1152];       // conv_out B frags (8 couts, 3 real)

// ---------------- helpers ----------------
__device__ __forceinline__ void mma_bf16(float& c0, float& c1, float& c2, float& c3,
                                         uint32_t a0, uint32_t a1, uint32_t a2, uint32_t a3,
                                         uint32_t b0, uint32_t b1) {
    asm volatile("mma.sync.aligned.m16n8k16.row.col.f32.bf16.bf16.f32 "
                 "{%0,%1,%2,%3}, {%4,%5,%6,%7}, {%8,%9}, {%0,%1,%2,%3};"
                 : "+f"(c0), "+f"(c1), "+f"(c2), "+f"(c3)
                 : "r"(a0), "r"(a1), "r"(a2), "r"(a3), "r"(b0), "r"(b1));
}
__device__ __forceinline__ void ldmA(uint32_t& r0, uint32_t& r1, uint32_t& r2, uint32_t& r3,
                                     uint32_t addr) {
    asm volatile("ldmatrix.sync.aligned.m8n8.x4.shared.b16 {%0,%1,%2,%3}, [%4];"
                 : "=r"(r0), "=r"(r1), "=r"(r2), "=r"(r3) : "r"(addr));
}
__device__ __forceinline__ uint32_t smem_u32(const void* p) {
    return (uint32_t)__cvta_generic_to_shared(p);
}
__device__ __forceinline__ void cp16(uint32_t dst, const void* src, int sz) {
    asm volatile("cp.async.cg.shared.global [%0], [%1], 16, %2;"
                 :: "r"(dst), "l"(src), "r"(sz));
}
__device__ __forceinline__ void cp4(uint32_t dst, const void* src, int sz) {
    asm volatile("cp.async.ca.shared.global [%0], [%1], 4, %2;"
                 :: "r"(dst), "l"(src), "r"(sz));
}
__device__ __forceinline__ void cp_commit_wait() {
    asm volatile("cp.async.commit_group;");
    asm volatile("cp.async.wait_group 0;");
}
// packed fp32x2
__device__ __forceinline__ unsigned long long pack2(float lo, float hi) {
    unsigned long long r;
    asm("mov.b64 %0, {%1, %2};" : "=l"(r) : "f"(lo), "f"(hi));
    return r;
}
__device__ __forceinline__ unsigned long long fma2(unsigned long long a,
                                                   unsigned long long b,
                                                   unsigned long long c) {
    unsigned long long d;
    asm("fma.rn.f32x2 %0, %1, %2, %3;" : "=l"(d) : "l"(a), "l"(b), "l"(c));
    return d;
}
__device__ __forceinline__ float lo2(unsigned long long v) {
    return __uint_as_float((unsigned)(v & 0xffffffffULL));
}
__device__ __forceinline__ float hi2(unsigned long long v) {
    return __uint_as_float((unsigned)(v >> 32));
}

// =====================================================================
// merged B prep: bf1 (3x1024) | bf2 (3x9216) | bf3 (3x4608) | bfo (1152)
// =====================================================================
__global__ void prep_all_k(const float* __restrict__ w1a, const float* __restrict__ w1b,
                           const float* __restrict__ w1c,
                           const float* __restrict__ w2a, const float* __restrict__ w2b,
                           const float* __restrict__ w2c,
                           const float* __restrict__ w3a, const float* __restrict__ w3b,
                           const float* __restrict__ w3c,
                           const float* __restrict__ wo,
                           uint32_t* __restrict__ bf1, uint32_t* __restrict__ bf2,
                           uint32_t* __restrict__ bf3, uint32_t* __restrict__ bfo)
{
    int gid = blockIdx.x*256 + threadIdx.x;

    if (gid < 3072) {                                   // conv1: im2col K=32 (27 real)
        int br = gid / 1024, idx = gid - br*1024;
        const float* wt = br == 0 ? w1a : (br == 1 ? w1b : w1c);
        int r    = idx & 3;
        int lane = (idx >> 2) & 31;
        int half = (idx >> 7) & 3;
        int kk   = idx >> 9;
        int n    = half*2 + (r >> 1);
        int breg = r & 1;
        int k0 = kk*16 + (lane & 3)*2 + breg*8;
        int co = n*8 + (lane >> 2);
        float v0 = 0.f, v1 = 0.f;
        if (k0 + 0 < 27) v0 = wt[(co*3 + (k0+0)/9)*9 + (k0+0)%9];
        if (k0 + 1 < 27) v1 = wt[(co*3 + (k0+1)/9)*9 + (k0+1)%9];
        __nv_bfloat162 pk = __floats2bfloat162_rn(v0, v1);
        bf1[gid] = *(uint32_t*)&pk;
        return;
    }
    gid -= 3072;
    if (gid < 27648) {                                  // conv2: CIN=64
        int br = gid / 9216, idx = gid - br*9216;
        const float* wt = br == 0 ? w2a : (br == 1 ? w2b : w2c);
        int r    = idx & 3;
        int lane = (idx >> 2) & 31;
        int half = (idx >> 7) & 1;
        int rest = idx >> 8;
        int kk   = rest & 1;
        int rest2 = rest >> 1;
        int dydx = rest2 % 9;
        int ch   = rest2 / 9;
        int n    = half*2 + (r >> 1);
        int breg = r & 1;
        int ci = ch*32 + kk*16 + (lane & 3)*2 + breg*8;
        int co = n*8 + (lane >> 2);
        __nv_bfloat162 pk = __floats2bfloat162_rn(
            wt[(co*64 + ci + 0)*9 + dydx], wt[(co*64 + ci + 1)*9 + dydx]);
        bf2[br*9216 + idx] = *(uint32_t*)&pk;
        return;
    }
    gid -= 27648;
    if (gid < 13824) {                                  // conv3: CIN=32
        int br = gid / 4608, idx = gid - br*4608;
        const float* wt = br == 0 ? w3a : (br == 1 ? w3b : w3c);
        int r    = idx & 3;
        int lane = (idx >> 2) & 31;
        int half = (idx >> 7) & 1;
        int rest = idx >> 8;
        int kk   = rest & 1;
        int dydx = rest >> 1;
        int n    = half*2 + (r >> 1);
        int breg = r & 1;
        int ci = kk*16 + (lane & 3)*2 + breg*8;
        int co = n*8 + (lane >> 2);
        __nv_bfloat162 pk = __floats2bfloat162_rn(
            wt[(co*32 + ci + 0)*9 + dydx], wt[(co*32 + ci + 1)*9 + dydx]);
        bf3[br*4608 + idx] = *(uint32_t*)&pk;
        return;
    }
    gid -= 13824;
    if (gid < 1152) {                                   // conv_out: 8 couts (3 real)
        int idx = gid;
        int breg = idx & 1;
        int lane = (idx >> 1) & 31;
        int kk   = (idx >> 6) & 1;
        int dydx = idx >> 7;
        int ci = kk*16 + (lane & 3)*2 + breg*8;
        int co = lane >> 2;
        float v0 = 0.f, v1 = 0.f;
        if (co < 3) {
            v0 = wo[(co*32 + ci + 0)*9 + dydx];
            v1 = wo[(co*32 + ci + 1)*9 + dydx];
        }
        __nv_bfloat162 pk = __floats2bfloat162_rn(v0, v1);
        bfo[idx] = *(uint32_t*)&pk;
    }
}

// =====================================================================
// conv1 fused: 3->64 x 3 branches. One fill + one im2col, 3 mainloops.
// =====================================================================
#define PADB 40

__global__ __launch_bounds__(256, 2)
void conv1_im2col_k(const float* __restrict__ in, const uint32_t* __restrict__ gB,
                    const float* __restrict__ bias0, const float* __restrict__ bias1,
                    const float* __restrict__ bias2, __nv_bfloat16* __restrict__ out)
{
    __shared__ float sRaw[3][4][132];
    __shared__ __align__(16) __nv_bfloat16 sA[256][PADB];

    const int bb = blockIdx.z;
    const int x0 = blockIdx.x * 128;
    const int y0 = blockIdx.y * 2;
    const int tid = threadIdx.x;
    const int warp = tid >> 5, lane = tid & 31;
    const int warpRow = warp >> 2;
    const int pxBase  = (warp & 3) * 32;
    const int groupId = lane >> 2, quad = lane & 3;

    for (int i = tid; i < 3*4*130; i += 256) {
        int ci = i / 520;
        int r2 = i - ci*520;
        int rr = r2 / 130;
        int xx = r2 - rr*130;
        int y = y0 - 1 + rr, x = x0 - 1 + xx;
        bool inb = ((unsigned)y < (unsigned)H) && ((unsigned)x < (unsigned)W);
        const float* src = in + ((size_t)(bb*3 + ci)*H + (inb ? y : 0))*W + (inb ? x : 0);
        cp4(smem_u32(&sRaw[ci][rr][xx]), src, inb ? 4 : 0);
    }
    cp_commit_wait();
    __syncthreads();

    {
        int r = tid >> 7, px = tid & 127;
        float vals[32];
        #pragma unroll
        for (int ci = 0; ci < 3; ci++)
            #pragma unroll
            for (int dy = 0; dy < 3; dy++)
                #pragma unroll
                for (int dx = 0; dx < 3; dx++)
                    vals[ci*9 + dy*3 + dx] = sRaw[ci][r + dy][px + dx];
        #pragma unroll
        for (int k = 27; k < 32; k++) vals[k] = 0.f;
        uint32_t pk[16];
        #pragma unroll
        for (int t = 0; t < 16; t++) {
            __nv_bfloat162 p = __floats2bfloat162_rn(vals[2*t], vals[2*t+1]);
            pk[t] = *(uint32_t*)&p;
        }
        uint4* dstp = (uint4*)&sA[tid][0];
        dstp[0] = make_uint4(pk[0],  pk[1],  pk[2],  pk[3]);
        dstp[1] = make_uint4(pk[4],  pk[5],  pk[6],  pk[7]);
        dstp[2] = make_uint4(pk[8],  pk[9],  pk[10], pk[11]);
        dstp[3] = make_uint4(pk[12], pk[13], pk[14], pk[15]);
    }
    __syncthreads();

    const uint32_t aLane = smem_u32(sA) +
        (uint32_t)((warpRow*128 + pxBase + (lane & 15))*(PADB*2) + (lane >> 4)*16);
    const int yOut = y0 + warpRow;

    #pragma unroll 1
    for (int br = 0; br < 3; br++) {
        const float* bias = br == 0 ? bias0 : (br == 1 ? bias1 : bias2);
        const uint4* pb4 = (const uint4*)(gB + br*1024) + lane;
        __nv_bfloat16* outp = out + (size_t)br * H1SZ;

        float acc[2][8][4];
        #pragma unroll
        for (int n = 0; n < 8; n++) {
            float b0 = __ldg(&bias[n*8 + quad*2 + 0]);
            float b1 = __ldg(&bias[n*8 + quad*2 + 1]);
            #pragma unroll
            for (int m = 0; m < 2; m++) {
                acc[m][n][0] = b0; acc[m][n][1] = b1;
                acc[m][n][2] = b0; acc[m][n][3] = b1;
            }
        }

        #pragma unroll
        for (int kk = 0; kk < 2; kk++) {
            uint4 L0 = __ldg(pb4 + kk*128);
            uint4 L1 = __ldg(pb4 + kk*128 + 32);
            uint4 L2 = __ldg(pb4 + kk*128 + 64);
            uint4 L3 = __ldg(pb4 + kk*128 + 96);
            #pragma unroll
            for (int m = 0; m < 2; m++) {
                uint32_t a0, a1, a2, a3;
                ldmA(a0, a1, a2, a3, aLane + (uint32_t)(m*16*(PADB*2) + kk*32));
                mma_bf16(acc[m][0][0], acc[m][0][1], acc[m][0][2], acc[m][0][3], a0,a1,a2,a3, L0.x, L0.y);
                mma_bf16(acc[m][1][0], acc[m][1][1], acc[m][1][2], acc[m][1][3], a0,a1,a2,a3, L0.z, L0.w);
                mma_bf16(acc[m][2][0], acc[m][2][1], acc[m][2][2], acc[m][2][3], a0,a1,a2,a3, L1.x, L1.y);
                mma_bf16(acc[m][3][0], acc[m][3][1], acc[m][3][2], acc[m][3][3], a0,a1,a2,a3, L1.z, L1.w);
                mma_bf16(acc[m][4][0], acc[m][4][1], acc[m][4][2], acc[m][4][3], a0,a1,a2,a3, L2.x, L2.y);
                mma_bf16(acc[m][5][0], acc[m][5][1], acc[m][5][2], acc[m][5][3], a0,a1,a2,a3, L2.z, L2.w);
                mma_bf16(acc[m][6][0], acc[m][6][1], acc[m][6][2], acc[m][6][3], a0,a1,a2,a3, L3.x, L3.y);
                mma_bf16(acc[m][7][0], acc[m][7][1], acc[m][7][2], acc[m][7][3], a0,a1,a2,a3, L3.z, L3.w);
            }
        }

        #pragma unroll
        for (int m = 0; m < 2; m++) {
            #pragma unroll
            for (int hh = 0; hh < 2; hh++) {
                int px = pxBase + m*16 + groupId + hh*8;
                __nv_bfloat16* op = outp + ((size_t)(bb*H + yOut)*W + x0 + px)*64 + quad*2;
                #pragma unroll
                for (int n = 0; n < 8; n++) {
                    float v0 = fmaxf(acc[m][n][hh*2 + 0], 0.f);
                    float v1 = fmaxf(acc[m][n][hh*2 + 1], 0.f);
                    *(__nv_bfloat162*)(op + n*8) = __floats2bfloat162_rn(v0, v1);
                }
            }
        }
    }
}

// =====================================================================
// bf16 implicit-GEMM conv (conv2/conv3): 4 rows x 128 px per block,
// 8 warps = 2/row x 4 rows, each warp 64 px (4 m16 tiles). Slab 6 rows.
// Per-branch launch (br is a parameter; z = batch) for L2 residency.
// =====================================================================
#define SMB4 (6*130*PADB*2)
#define SMB  (4*130*PADB*2)

template<int KSTEPS, int NCHUNK, int CINTOT, int OSTR, bool RELU, bool FEAT>
__global__ __launch_bounds__(256, 2)
void gemm_bf16_k(const __nv_bfloat16* __restrict__ in, const uint32_t* __restrict__ gB,
                 const float* __restrict__ bias, __nv_bfloat16* __restrict__ out,
                 int br)
{
    extern __shared__ __align__(16) char sAb[];
    const int outOff = FEAT ? br*32 : 0;

    const int bb = blockIdx.z;
    const int x0 = blockIdx.x * 128;
    const int y0 = blockIdx.y * 4;
    const int tid = threadIdx.x;
    const int warp = tid >> 5, lane = tid & 31;
    const int warpRow = warp >> 1;          // 0..3
    const int pxBase  = (warp & 1) * 64;    // 0 or 64
    const int groupId = lane >> 2, quad = lane & 3;

    const uint32_t aLane = smem_u32(sAb) + (uint32_t)((lane & 15)*(PADB*2) + (lane >> 4)*16);

    float acc[4][4][4];
    #pragma unroll
    for (int n = 0; n < 4; n++) {
        float b0 = __ldg(&bias[n*8 + quad*2 + 0]);
        float b1 = __ldg(&bias[n*8 + quad*2 + 1]);
        #pragma unroll
        for (int m = 0; m < 4; m++) {
            acc[m][n][0] = b0; acc[m][n][1] = b1;
            acc[m][n][2] = b0; acc[m][n][3] = b1;
        }
    }

    #pragma unroll 1
    for (int ch = 0; ch < NCHUNK; ch++) {
        __syncthreads();
        #pragma unroll
        for (int r = 0; r < 6; r++) {
            int y = y0 - 1 + r;
            bool yin = (unsigned)y < (unsigned)H;
            for (int i = tid; i < 130*4; i += 256) {
                int px = i >> 2, v = i & 3;
                int x = x0 - 1 + px;
                bool inb = yin && ((unsigned)x < (unsigned)W);
                const __nv_bfloat16* src = in +
                    ((size_t)(bb*H + (inb ? y : 0))*W + (inb ? x : 0))*CINTOT + ch*32 + v*8;
                cp16(smem_u32(sAb + (size_t)(r*130 + px)*(PADB*2) + v*16), src, inb ? 16 : 0);
            }
        }
        cp_commit_wait();
        __syncthreads();

        #pragma unroll
        for (int dy = 0; dy < 3; dy++) {
            #pragma unroll
            for (int dx = 0; dx < 3; dx++) {
                const uint32_t aBase = aLane +
                    (uint32_t)(((warpRow + dy)*130 + pxBase + dx)*(PADB*2));
                const uint4* pb4 = (const uint4*)gB + ((ch*9 + dy*3 + dx)*KSTEPS)*64 + lane;
                #pragma unroll
                for (int kk = 0; kk < KSTEPS; kk++) {
                    uint4 L0 = __ldg(pb4 + kk*64);
                    uint4 L1 = __ldg(pb4 + kk*64 + 32);
                    #pragma unroll
                    for (int m = 0; m < 4; m++) {
                        uint32_t a0, a1, a2, a3;
                        ldmA(a0, a1, a2, a3, aBase + (uint32_t)(m*16*(PADB*2) + kk*32));
                        mma_bf16(acc[m][0][0], acc[m][0][1], acc[m][0][2], acc[m][0][3],
                                 a0, a1, a2, a3, L0.x, L0.y);
                        mma_bf16(acc[m][1][0], acc[m][1][1], acc[m][1][2], acc[m][1][3],
                                 a0, a1, a2, a3, L0.z, L0.w);
                        mma_bf16(acc[m][2][0], acc[m][2][1], acc[m][2][2], acc[m][2][3],
                                 a0, a1, a2, a3, L1.x, L1.y);
                        mma_bf16(acc[m][3][0], acc[m][3][1], acc[m][3][2], acc[m][3][3],
                                 a0, a1, a2, a3, L1.z, L1.w);
                    }
                }
            }
        }
    }

    const int yOut = y0 + warpRow;
    #pragma unroll
    for (int m = 0; m < 4; m++) {
        #pragma unroll
        for (int hh = 0; hh < 2; hh++) {
            int px = pxBase + m*16 + groupId + hh*8;
            __nv_bfloat16* op = out + ((size_t)(bb*H + yOut)*W + x0 + px)*OSTR + outOff + quad*2;
            #pragma unroll
            for (int n = 0; n < 4; n++) {
                float v0 = acc[m][n][hh*2 + 0];
                float v1 = acc[m][n][hh*2 + 1];
                if (RELU) { v0 = fmaxf(v0, 0.f); v1 = fmaxf(v1, 0.f); }
                *(__nv_bfloat162*)(op + n*8) = __floats2bfloat162_rn(v0, v1);
            }
        }
    }
}

// =====================================================================
// shifted-window attention: 2 windows/block (128 thr), f32x2 packed math
// =====================================================================
__global__ __launch_bounds__(128)
void attn_k(const __nv_bfloat16* __restrict__ feat, const float* __restrict__ pos,
            __nv_bfloat16* __restrict__ aout)
{
    __shared__ float sK[2][64][32];
    __shared__ float sV[2][64][32];
    __shared__ float sPos[225];

    const int bb = blockIdx.y;
    const int tid = threadIdx.x;
    const int sub = tid >> 6;           // which window half
    const int t64 = tid & 63;
    const int w   = blockIdx.x*2 + sub;
    const int wh = w / NWIN, ww = w - wh*NWIN;
    const int iy = t64 >> 3, ix = t64 & 7;
    const int sy = wh*8 + iy, sx = ww*8 + ix;
    int y = sy + 4; if (y >= H) y -= H;
    int x = sx + 4; if (x >= W) x -= W;

    for (int idx = t64; idx < 64*4; idx += 64) {
        int j = idx >> 2, part = idx & 3;
        int jy = j >> 3, jx = j & 7;
        int yy = wh*8 + jy + 4; if (yy >= H) yy -= H;
        int xx = ww*8 + jx + 4; if (xx >= W) xx -= W;
        const __nv_bfloat16* p = feat + ((size_t)(bb*H + yy)*W + xx)*96;
        uint4 uk = *(const uint4*)(p + 32 + part*8);
        uint4 uv = *(const uint4*)(p + 64 + part*8);
        const __nv_bfloat162* hk = (const __nv_bfloat162*)&uk;
        const __nv_bfloat162* hv = (const __nv_bfloat162*)&uv;
        #pragma unroll
        for (int t = 0; t < 4; t++) {
            float2 fk = __bfloat1622float2(hk[t]);
            float2 fv = __bfloat1622float2(hv[t]);
            sK[sub][j][part*8 + t*2 + 0] = fk.x;
            sK[sub][j][part*8 + t*2 + 1] = fk.y;
            sV[sub][j][part*8 + t*2 + 0] = fv.x;
            sV[sub][j][part*8 + t*2 + 1] = fv.y;
        }
    }
    for (int idx = tid; idx < 225; idx += 128) sPos[idx] = pos[idx];

    unsigned long long q2[16];
    {
        const __nv_bfloat16* fp = feat + ((size_t)(bb*H + y)*W + x)*96;
        #pragma unroll
        for (int part = 0; part < 4; part++) {
            uint4 u = *(const uint4*)(fp + part*8);
            const __nv_bfloat162* hq = (const __nv_bfloat162*)&u;
            #pragma unroll
            for (int t = 0; t < 4; t++) {
                float2 f = __bfloat1622float2(hq[t]);
                q2[part*4 + t] = pack2(f.x, f.y);
            }
        }
    }
    __syncthreads();

    const bool mR = (wh == NWIN-1);
    const bool mC = (ww == NWIN-1);
    const float scale = 0.35355339059327373f;
    const int posOff = (7 - iy)*15 + (7 - ix);

    __nv_bfloat16* op = aout + ((size_t)(bb*H + sy)*W + sx)*32;

    #pragma unroll 1
    for (int h = 0; h < 4; h++) {
        float lg[64];
        float mx = -1e30f;
        #pragma unroll
        for (int j = 0; j < 64; j++) {
            const int jy = j >> 3, jx = j & 7;
            const unsigned long long* kp = (const unsigned long long*)&sK[sub][j][h*8];
            unsigned long long d2 = fma2(q2[h*4+0], kp[0], 0ULL);
            d2 = fma2(q2[h*4+1], kp[1], d2);
            d2 = fma2(q2[h*4+2], kp[2], d2);
            d2 = fma2(q2[h*4+3], kp[3], d2);
            float l = (lo2(d2) + hi2(d2))*scale + sPos[jy*15 + jx + posOff];
            bool msk = (mR && ((iy >= 4) != (jy >= 4))) ||
                       (mC && ((ix >= 4) != (jx >= 4)));
            l = msk ? -1e30f : l;
            lg[j] = l;
            mx = fmaxf(mx, l);
        }
        float s = 0.f;
        #pragma unroll
        for (int j = 0; j < 64; j++) {
            float e = __expf(lg[j] - mx);
            lg[j] = e;
            s += e;
        }
        const float inv = 1.f / s;
        unsigned long long oh2[4];
        #pragma unroll
        for (int d = 0; d < 4; d++) oh2[d] = 0ULL;
        #pragma unroll
        for (int j = 0; j < 64; j++) {
            unsigned long long pp = pack2(lg[j], lg[j]);
            const unsigned long long* vp = (const unsigned long long*)&sV[sub][j][h*8];
            oh2[0] = fma2(pp, vp[0], oh2[0]);
            oh2[1] = fma2(pp, vp[1], oh2[1]);
            oh2[2] = fma2(pp, vp[2], oh2[2]);
            oh2[3] = fma2(pp, vp[3], oh2[3]);
        }
        #pragma unroll
        for (int d = 0; d < 4; d++)
            *(__nv_bfloat162*)(op + h*8 + d*2) =
                __floats2bfloat162_rn(lo2(oh2[d])*inv, hi2(oh2[d])*inv);
    }
}

// =====================================================================
// conv_out GEMM (32->3, 8 couts padded) + roll(+4,+4) + residual, fp32 out
// =====================================================================
__global__ __launch_bounds__(256, 3)
void convout_gemm_k(const __nv_bfloat16* __restrict__ in, const uint32_t* __restrict__ gB,
                    const float* __restrict__ bias, const float* __restrict__ xin,
                    float* __restrict__ out)
{
    extern __shared__ __align__(16) char sAb[];

    const int bb = blockIdx.z;
    const int x0 = blockIdx.x * 128;
    const int y0 = blockIdx.y * 2;
    const int tid = threadIdx.x;
    const int warp = tid >> 5, lane = tid & 31;
    const int warpRow = warp >> 2;
    const int pxBase  = (warp & 3) * 32;
    const int groupId = lane >> 2, quad = lane & 3;

    const uint32_t aLane = smem_u32(sAb) + (uint32_t)((lane & 15)*(PADB*2) + (lane >> 4)*16);

    const int co0 = quad*2, co1 = quad*2 + 1;
    float acc[2][4];
    {
        float b0 = co0 < 3 ? __ldg(&bias[co0]) : 0.f;
        float b1 = co1 < 3 ? __ldg(&bias[co1]) : 0.f;
        #pragma unroll
        for (int m = 0; m < 2; m++) {
            acc[m][0] = b0; acc[m][1] = b1;
            acc[m][2] = b0; acc[m][3] = b1;
        }
    }

    #pragma unroll
    for (int r = 0; r < 4; r++) {
        int y = y0 - 1 + r;
        bool yin = (unsigned)y < (unsigned)H;
        for (int i = tid; i < 130*4; i += 256) {
            int px = i >> 2, v = i & 3;
            int x = x0 - 1 + px;
            bool inb = yin && ((unsigned)x < (unsigned)W);
            const __nv_bfloat16* src = in +
                ((size_t)(bb*H + (inb ? y : 0))*W + (inb ? x : 0))*32 + v*8;
            cp16(smem_u32(sAb + (size_t)(r*130 + px)*(PADB*2) + v*16), src, inb ? 16 : 0);
        }
    }
    cp_commit_wait();
    __syncthreads();

    #pragma unroll
    for (int dy = 0; dy < 3; dy++) {
        #pragma unroll
        for (int dx = 0; dx < 3; dx++) {
            const uint32_t aBase = aLane +
                (uint32_t)(((warpRow + dy)*130 + pxBase + dx)*(PADB*2));
            const uint2* pb2 = (const uint2*)gB + (dy*3 + dx)*2*32 + lane;
            #pragma unroll
            for (int kk = 0; kk < 2; kk++) {
                uint2 L = __ldg(pb2 + kk*32);
                #pragma unroll
                for (int m = 0; m < 2; m++) {
                    uint32_t a0, a1, a2, a3;
                    ldmA(a0, a1, a2, a3, aBase + (uint32_t)(m*16*(PADB*2) + kk*32));
                    mma_bf16(acc[m][0], acc[m][1], acc[m][2], acc[m][3],
                             a0, a1, a2, a3, L.x, L.y);
                }
            }
        }
    }

    const int gy = y0 + warpRow;
    int oy = gy + 4; if (oy >= H) oy -= H;
    #pragma unroll
    for (int m = 0; m < 2; m++) {
        #pragma unroll
        for (int hh = 0; hh < 2; hh++) {
            int gx = x0 + pxBase + m*16 + groupId + hh*8;
            int ox = gx + 4; if (ox >= W) ox -= W;
            if (co0 < 3) {
                size_t idx = ((size_t)(bb*3 + co0)*H + oy)*W + ox;
                out[idx] = xin[idx] + acc[m][hh*2 + 0];
            }
            if (co1 < 3) {
                size_t idx = ((size_t)(bb*3 + co1)*H + oy)*W + ox;
                out[idx] = xin[idx] + acc[m][hh*2 + 1];
            }
        }
    }
}

// ---------------- launcher ----------------
extern "C" void kernel_launch(void* const* d_in, const int* in_sizes, int n_in,
                              void* d_out, int out_size)
{
    (void)in_sizes; (void)n_in; (void)out_size;
    const float* x   = (const float*)d_in[0];
    const float* wo  = (const float*)d_in[19];
    const float* bo  = (const float*)d_in[20];
    const float* pos = (const float*)d_in[21];
    float* out = (float*)d_out;

    __nv_bfloat16 *h1, *h2, *feat, *aout;
    uint32_t *bf1, *bf2, *bf3, *bfo;
    cudaGetSymbolAddress((void**)&h1,   g_h1);
    cudaGetSymbolAddress((void**)&h2,   g_h2);
    cudaGetSymbolAddress((void**)&feat, g_feat);
    cudaGetSymbolAddress((void**)&aout, g_aout);
    cudaGetSymbolAddress((void**)&bf1,  g_bf1);
    cudaGetSymbolAddress((void**)&bf2,  g_bf2);
    cudaGetSymbolAddress((void**)&bf3,  g_bf3);
    cudaGetSymbolAddress((void**)&bfo,  g_bfo);

    // 6-row slabs exceed 48KB default dynamic smem limit
    cudaFuncSetAttribute((const void*)gemm_bf16_k<2,2,64,32,true,false>,
                         cudaFuncAttributeMaxDynamicSharedMemorySize, SMB4);
    cudaFuncSetAttribute((const void*)gemm_bf16_k<2,1,32,96,false,true>,
                         cudaFuncAttributeMaxDynamicSharedMemorySize, SMB4);

    // single merged B prep (45696 elements)
    prep_all_k<<<179, 256>>>(
        (const float*)d_in[1], (const float*)d_in[7],  (const float*)d_in[13],
        (const float*)d_in[3], (const float*)d_in[9],  (const float*)d_in[15],
        (const float*)d_in[5], (const float*)d_in[11], (const float*)d_in[17],
        wo, bf1, bf2, bf3, bfo);

    dim3 g1(W/128, H/2, BATCH);     // conv1 fused: z = bb
    dim3 gb(W/128, H/4, BATCH);     // per-branch conv2/conv3 4-row tiles

    conv1_im2col_k<<<g1, 256>>>(
        x, bf1,
        (const float*)d_in[2], (const float*)d_in[8], (const float*)d_in[14], h1);

    // producer->consumer interleave per branch: h1(br)/h2(br) stay L2-resident
    for (int br = 0; br < 3; br++) {
        gemm_bf16_k<2, 2, 64, 32, true,  false><<<gb, 256, SMB4>>>(
            h1 + (size_t)br*H1SZ, bf2 + br*9216,
            (const float*)d_in[4 + 6*br], h2 + (size_t)br*H2SZ, br);
        gemm_bf16_k<2, 1, 32, 96, false, true ><<<gb, 256, SMB4>>>(
            h2 + (size_t)br*H2SZ, bf3 + br*4608,
            (const float*)d_in[6 + 6*br], feat, br);
    }

    attn_k<<<dim3(NWIN*NWIN/2, BATCH), 128>>>(feat, pos, aout);
    convout_gemm_k<<<g1, 256, SMB>>>(aout, bfo, bo, x, out);
}

// round 16
// speedup vs baseline: 1.0539x; 1.0539x over previous
#include <cuda_runtime.h>
#include <cuda_bf16.h>
#include <cstdint>
#include <cstddef>

#define H 384
#define W 384
#define BATCH 2
#define NWIN 48

#define H1SZ ((size_t)BATCH*H*W*64)   // elements per branch (bf16)
#define H2SZ ((size_t)BATCH*H*W*32)

// ---------------- scratch ----------------
__device__ __nv_bfloat16 g_h1[3*H1SZ];
__device__ __nv_bfloat16 g_h2[3*H2SZ];
__device__ __nv_bfloat16 g_feat[(size_t)BATCH*H*W*96];
__device__ __nv_bfloat16 g_aout[(size_t)BATCH*H*W*32];   // channel-last, shifted space
__device__ uint32_t g_bf1[3*1024];     // conv1 B frags (bf16x2, im2col K=32)
__device__ uint32_t g_bf2[3*9216];     // conv2 B frags
__device__ uint32_t g_bf3[3*4608];     // conv3 B frags
__device__ uint32_t g_bfo[1152];       // conv_out B frags (8 couts, 3 real)

// ---------------- helpers ----------------
__device__ __forceinline__ void mma_bf16(float& c0, float& c1, float& c2, float& c3,
                                         uint32_t a0, uint32_t a1, uint32_t a2, uint32_t a3,
                                         uint32_t b0, uint32_t b1) {
    asm volatile("mma.sync.aligned.m16n8k16.row.col.f32.bf16.bf16.f32 "
                 "{%0,%1,%2,%3}, {%4,%5,%6,%7}, {%8,%9}, {%0,%1,%2,%3};"
                 : "+f"(c0), "+f"(c1), "+f"(c2), "+f"(c3)
                 : "r"(a0), "r"(a1), "r"(a2), "r"(a3), "r"(b0), "r"(b1));
}
__device__ __forceinline__ void ldmA(uint32_t& r0, uint32_t& r1, uint32_t& r2, uint32_t& r3,
                                     uint32_t addr) {
    asm volatile("ldmatrix.sync.aligned.m8n8.x4.shared.b16 {%0,%1,%2,%3}, [%4];"
                 : "=r"(r0), "=r"(r1), "=r"(r2), "=r"(r3) : "r"(addr));
}
__device__ __forceinline__ uint32_t smem_u32(const void* p) {
    return (uint32_t)__cvta_generic_to_shared(p);
}
__device__ __forceinline__ void cp16(uint32_t dst, const void* src, int sz) {
    asm volatile("cp.async.cg.shared.global [%0], [%1], 16, %2;"
                 :: "r"(dst), "l"(src), "r"(sz));
}
__device__ __forceinline__ void cp_commit_wait() {
    asm volatile("cp.async.commit_group;");
    asm volatile("cp.async.wait_group 0;");
}
// packed fp32x2
__device__ __forceinline__ unsigned long long pack2(float lo, float hi) {
    unsigned long long r;
    asm("mov.b64 %0, {%1, %2};" : "=l"(r) : "f"(lo), "f"(hi));
    return r;
}
__device__ __forceinline__ unsigned long long fma2(unsigned long long a,
                                                   unsigned long long b,
                                                   unsigned long long c) {
    unsigned long long d;
    asm("fma.rn.f32x2 %0, %1, %2, %3;" : "=l"(d) : "l"(a), "l"(b), "l"(c));
    return d;
}
__device__ __forceinline__ float lo2(unsigned long long v) {
    return __uint_as_float((unsigned)(v & 0xffffffffULL));
}
__device__ __forceinline__ float hi2(unsigned long long v) {
    return __uint_as_float((unsigned)(v >> 32));
}

// =====================================================================
// merged B prep: bf1 (3x1024) | bf2 (3x9216) | bf3 (3x4608) | bfo (1152)
// =====================================================================
__global__ void prep_all_k(const float* __restrict__ w1a, const float* __restrict__ w1b,
                           const float* __restrict__ w1c,
                           const float* __restrict__ w2a, const float* __restrict__ w2b,
                           const float* __restrict__ w2c,
                           const float* __restrict__ w3a, const float* __restrict__ w3b,
                           const float* __restrict__ w3c,
                           const float* __restrict__ wo,
                           uint32_t* __restrict__ bf1, uint32_t* __restrict__ bf2,
                           uint32_t* __restrict__ bf3, uint32_t* __restrict__ bfo)
{
    int gid = blockIdx.x*256 + threadIdx.x;

    if (gid < 3072) {                                   // conv1: im2col K=32 (27 real)
        int br = gid / 1024, idx = gid - br*1024;
        const float* wt = br == 0 ? w1a : (br == 1 ? w1b : w1c);
        int r    = idx & 3;
        int lane = (idx >> 2) & 31;
        int half = (idx >> 7) & 3;
        int kk   = idx >> 9;
        int n    = half*2 + (r >> 1);
        int breg = r & 1;
        int k0 = kk*16 + (lane & 3)*2 + breg*8;
        int co = n*8 + (lane >> 2);
        float v0 = 0.f, v1 = 0.f;
        if (k0 + 0 < 27) v0 = wt[(co*3 + (k0+0)/9)*9 + (k0+0)%9];
        if (k0 + 1 < 27) v1 = wt[(co*3 + (k0+1)/9)*9 + (k0+1)%9];
        __nv_bfloat162 pk = __floats2bfloat162_rn(v0, v1);
        bf1[gid] = *(uint32_t*)&pk;
        return;
    }
    gid -= 3072;
    if (gid < 27648) {                                  // conv2: CIN=64
        int br = gid / 9216, idx = gid - br*9216;
        const float* wt = br == 0 ? w2a : (br == 1 ? w2b : w2c);
        int r    = idx & 3;
        int lane = (idx >> 2) & 31;
        int half = (idx >> 7) & 1;
        int rest = idx >> 8;
        int kk   = rest & 1;
        int rest2 = rest >> 1;
        int dydx = rest2 % 9;
        int ch   = rest2 / 9;
        int n    = half*2 + (r >> 1);
        int breg = r & 1;
        int ci = ch*32 + kk*16 + (lane & 3)*2 + breg*8;
        int co = n*8 + (lane >> 2);
        __nv_bfloat162 pk = __floats2bfloat162_rn(
            wt[(co*64 + ci + 0)*9 + dydx], wt[(co*64 + ci + 1)*9 + dydx]);
        bf2[br*9216 + idx] = *(uint32_t*)&pk;
        return;
    }
    gid -= 27648;
    if (gid < 13824) {                                  // conv3: CIN=32
        int br = gid / 4608, idx = gid - br*4608;
        const float* wt = br == 0 ? w3a : (br == 1 ? w3b : w3c);
        int r    = idx & 3;
        int lane = (idx >> 2) & 31;
        int half = (idx >> 7) & 1;
        int rest = idx >> 8;
        int kk   = rest & 1;
        int dydx = rest >> 1;
        int n    = half*2 + (r >> 1);
        int breg = r & 1;
        int ci = kk*16 + (lane & 3)*2 + breg*8;
        int co = n*8 + (lane >> 2);
        __nv_bfloat162 pk = __floats2bfloat162_rn(
            wt[(co*32 + ci + 0)*9 + dydx], wt[(co*32 + ci + 1)*9 + dydx]);
        bf3[br*4608 + idx] = *(uint32_t*)&pk;
        return;
    }
    gid -= 13824;
    if (gid < 1152) {                                   // conv_out: 8 couts (3 real)
        int idx = gid;
        int breg = idx & 1;
        int lane = (idx >> 1) & 31;
        int kk   = (idx >> 6) & 1;
        int dydx = idx >> 7;
        int ci = kk*16 + (lane & 3)*2 + breg*8;
        int co = lane >> 2;
        float v0 = 0.f, v1 = 0.f;
        if (co < 3) {
            v0 = wo[(co*32 + ci + 0)*9 + dydx];
            v1 = wo[(co*32 + ci + 1)*9 + dydx];
        }
        __nv_bfloat162 pk = __floats2bfloat162_rn(v0, v1);
        bfo[idx] = *(uint32_t*)&pk;
    }
}

// =====================================================================
// conv1 fused: 3->64 x 3 branches. One vectorized fill + one im2col,
// A-fragments hoisted out of the branch loop.
// =====================================================================
#define PADB 40

__global__ __launch_bounds__(256, 2)
void conv1_im2col_k(const float* __restrict__ in, const uint32_t* __restrict__ gB,
                    const float* __restrict__ bias0, const float* __restrict__ bias1,
                    const float* __restrict__ bias2, __nv_bfloat16* __restrict__ out)
{
    __shared__ __align__(16) float sRaw[3][4][136];   // xx=0 <-> global x0-4
    __shared__ __align__(16) __nv_bfloat16 sA[256][PADB];

    const int bb = blockIdx.z;
    const int x0 = blockIdx.x * 128;
    const int y0 = blockIdx.y * 2;
    const int tid = threadIdx.x;
    const int warp = tid >> 5, lane = tid & 31;
    const int warpRow = warp >> 2;
    const int pxBase  = (warp & 3) * 32;
    const int groupId = lane >> 2, quad = lane & 3;

    // vectorized fill: 3 ci x 4 rows x 33 granules of 16B (x0-4 .. x0+127)
    for (int i = tid; i < 3*4*33; i += 256) {
        int ci = i / 132;
        int r2 = i - ci*132;
        int rr = r2 / 33;
        int g  = r2 - rr*33;
        int y  = y0 - 1 + rr;
        int xg = x0 - 4 + g*4;
        bool inb = ((unsigned)y < (unsigned)H) && (xg >= 0);
        const float* src = in + ((size_t)(bb*3 + ci)*H + (inb ? y : 0))*W + (inb ? xg : 0);
        cp16(smem_u32(&sRaw[ci][rr][g*4]), src, inb ? 16 : 0);
    }
    cp_commit_wait();
    __syncthreads();

    // im2col build (once): sRaw x-index = (x - (x0-4)) = px + 4 + (dx-1)
    {
        int r = tid >> 7, px = tid & 127;
        float vals[32];
        #pragma unroll
        for (int ci = 0; ci < 3; ci++)
            #pragma unroll
            for (int dy = 0; dy < 3; dy++)
                #pragma unroll
                for (int dx = 0; dx < 3; dx++)
                    vals[ci*9 + dy*3 + dx] = sRaw[ci][r + dy][px + 3 + dx];
        #pragma unroll
        for (int k = 27; k < 32; k++) vals[k] = 0.f;
        uint32_t pk[16];
        #pragma unroll
        for (int t = 0; t < 16; t++) {
            __nv_bfloat162 p = __floats2bfloat162_rn(vals[2*t], vals[2*t+1]);
            pk[t] = *(uint32_t*)&p;
        }
        uint4* dstp = (uint4*)&sA[tid][0];
        dstp[0] = make_uint4(pk[0],  pk[1],  pk[2],  pk[3]);
        dstp[1] = make_uint4(pk[4],  pk[5],  pk[6],  pk[7]);
        dstp[2] = make_uint4(pk[8],  pk[9],  pk[10], pk[11]);
        dstp[3] = make_uint4(pk[12], pk[13], pk[14], pk[15]);
    }
    __syncthreads();

    const uint32_t aLane = smem_u32(sA) +
        (uint32_t)((warpRow*128 + pxBase + (lane & 15))*(PADB*2) + (lane >> 4)*16);
    const int yOut = y0 + warpRow;

    // hoist A fragments once (identical for all 3 branches)
    uint32_t afr[2][2][4];
    #pragma unroll
    for (int kk = 0; kk < 2; kk++)
        #pragma unroll
        for (int m = 0; m < 2; m++)
            ldmA(afr[kk][m][0], afr[kk][m][1], afr[kk][m][2], afr[kk][m][3],
                 aLane + (uint32_t)(m*16*(PADB*2) + kk*32));

    #pragma unroll 1
    for (int br = 0; br < 3; br++) {
        const float* bias = br == 0 ? bias0 : (br == 1 ? bias1 : bias2);
        const uint4* pb4 = (const uint4*)(gB + br*1024) + lane;
        __nv_bfloat16* outp = out + (size_t)br * H1SZ;

        float acc[2][8][4];
        #pragma unroll
        for (int n = 0; n < 8; n++) {
            float b0 = __ldg(&bias[n*8 + quad*2 + 0]);
            float b1 = __ldg(&bias[n*8 + quad*2 + 1]);
            #pragma unroll
            for (int m = 0; m < 2; m++) {
                acc[m][n][0] = b0; acc[m][n][1] = b1;
                acc[m][n][2] = b0; acc[m][n][3] = b1;
            }
        }

        #pragma unroll
        for (int kk = 0; kk < 2; kk++) {
            uint4 L0 = __ldg(pb4 + kk*128);
            uint4 L1 = __ldg(pb4 + kk*128 + 32);
            uint4 L2 = __ldg(pb4 + kk*128 + 64);
            uint4 L3 = __ldg(pb4 + kk*128 + 96);
            #pragma unroll
            for (int m = 0; m < 2; m++) {
                uint32_t a0 = afr[kk][m][0], a1 = afr[kk][m][1];
                uint32_t a2 = afr[kk][m][2], a3 = afr[kk][m][3];
                mma_bf16(acc[m][0][0], acc[m][0][1], acc[m][0][2], acc[m][0][3], a0,a1,a2,a3, L0.x, L0.y);
                mma_bf16(acc[m][1][0], acc[m][1][1], acc[m][1][2], acc[m][1][3], a0,a1,a2,a3, L0.z, L0.w);
                mma_bf16(acc[m][2][0], acc[m][2][1], acc[m][2][2], acc[m][2][3], a0,a1,a2,a3, L1.x, L1.y);
                mma_bf16(acc[m][3][0], acc[m][3][1], acc[m][3][2], acc[m][3][3], a0,a1,a2,a3, L1.z, L1.w);
                mma_bf16(acc[m][4][0], acc[m][4][1], acc[m][4][2], acc[m][4][3], a0,a1,a2,a3, L2.x, L2.y);
                mma_bf16(acc[m][5][0], acc[m][5][1], acc[m][5][2], acc[m][5][3], a0,a1,a2,a3, L2.z, L2.w);
                mma_bf16(acc[m][6][0], acc[m][6][1], acc[m][6][2], acc[m][6][3], a0,a1,a2,a3, L3.x, L3.y);
                mma_bf16(acc[m][7][0], acc[m][7][1], acc[m][7][2], acc[m][7][3], a0,a1,a2,a3, L3.z, L3.w);
            }
        }

        #pragma unroll
        for (int m = 0; m < 2; m++) {
            #pragma unroll
            for (int hh = 0; hh < 2; hh++) {
                int px = pxBase + m*16 + groupId + hh*8;
                __nv_bfloat16* op = outp + ((size_t)(bb*H + yOut)*W + x0 + px)*64 + quad*2;
                #pragma unroll
                for (int n = 0; n < 8; n++) {
                    float v0 = fmaxf(acc[m][n][hh*2 + 0], 0.f);
                    float v1 = fmaxf(acc[m][n][hh*2 + 1], 0.f);
                    *(__nv_bfloat162*)(op + n*8) = __floats2bfloat162_rn(v0, v1);
                }
            }
        }
    }
}

// =====================================================================
// bf16 implicit-GEMM conv (conv2/conv3): 4 rows x 128 px per block,
// fused z = br*2 + bb (R14 winner structure). Slab 6 rows.
// =====================================================================
#define SMB4 (6*130*PADB*2)
#define SMB  (4*130*PADB*2)

template<int KSTEPS, int NCHUNK, int CINTOT, int OSTR, bool RELU, bool FEAT>
__global__ __launch_bounds__(256, 2)
void gemm_bf16_k(const __nv_bfloat16* __restrict__ in, const uint32_t* __restrict__ gB,
                 const float* __restrict__ bias0, const float* __restrict__ bias1,
                 const float* __restrict__ bias2, __nv_bfloat16* __restrict__ out,
                 size_t inStride, size_t outStride)
{
    extern __shared__ __align__(16) char sAb[];
    constexpr int BSZ = NCHUNK*9*KSTEPS*256;

    const int z  = blockIdx.z;
    const int bb = z & 1;
    const int br = z >> 1;
    const float* bias = br == 0 ? bias0 : (br == 1 ? bias1 : bias2);
    in  += (size_t)br * inStride;
    out += (size_t)br * outStride;
    gB  += br * BSZ;
    const int outOff = FEAT ? br*32 : 0;

    const int x0 = blockIdx.x * 128;
    const int y0 = blockIdx.y * 4;
    const int tid = threadIdx.x;
    const int warp = tid >> 5, lane = tid & 31;
    const int warpRow = warp >> 1;          // 0..3
    const int pxBase  = (warp & 1) * 64;    // 0 or 64
    const int groupId = lane >> 2, quad = lane & 3;

    const uint32_t aLane = smem_u32(sAb) + (uint32_t)((lane & 15)*(PADB*2) + (lane >> 4)*16);

    float acc[4][4][4];
    #pragma unroll
    for (int n = 0; n < 4; n++) {
        float b0 = __ldg(&bias[n*8 + quad*2 + 0]);
        float b1 = __ldg(&bias[n*8 + quad*2 + 1]);
        #pragma unroll
        for (int m = 0; m < 4; m++) {
            acc[m][n][0] = b0; acc[m][n][1] = b1;
            acc[m][n][2] = b0; acc[m][n][3] = b1;
        }
    }

    #pragma unroll 1
    for (int ch = 0; ch < NCHUNK; ch++) {
        __syncthreads();
        #pragma unroll
        for (int r = 0; r < 6; r++) {
            int y = y0 - 1 + r;
            bool yin = (unsigned)y < (unsigned)H;
            for (int i = tid; i < 130*4; i += 256) {
                int px = i >> 2, v = i & 3;
                int x = x0 - 1 + px;
                bool inb = yin && ((unsigned)x < (unsigned)W);
                const __nv_bfloat16* src = in +
                    ((size_t)(bb*H + (inb ? y : 0))*W + (inb ? x : 0))*CINTOT + ch*32 + v*8;
                cp16(smem_u32(sAb + (size_t)(r*130 + px)*(PADB*2) + v*16), src, inb ? 16 : 0);
            }
        }
        cp_commit_wait();
        __syncthreads();

        #pragma unroll
        for (int dy = 0; dy < 3; dy++) {
            #pragma unroll
            for (int dx = 0; dx < 3; dx++) {
                const uint32_t aBase = aLane +
                    (uint32_t)(((warpRow + dy)*130 + pxBase + dx)*(PADB*2));
                const uint4* pb4 = (const uint4*)gB + ((ch*9 + dy*3 + dx)*KSTEPS)*64 + lane;
                #pragma unroll
                for (int kk = 0; kk < KSTEPS; kk++) {
                    uint4 L0 = __ldg(pb4 + kk*64);
                    uint4 L1 = __ldg(pb4 + kk*64 + 32);
                    #pragma unroll
                    for (int m = 0; m < 4; m++) {
                        uint32_t a0, a1, a2, a3;
                        ldmA(a0, a1, a2, a3, aBase + (uint32_t)(m*16*(PADB*2) + kk*32));
                        mma_bf16(acc[m][0][0], acc[m][0][1], acc[m][0][2], acc[m][0][3],
                                 a0, a1, a2, a3, L0.x, L0.y);
                        mma_bf16(acc[m][1][0], acc[m][1][1], acc[m][1][2], acc[m][1][3],
                                 a0, a1, a2, a3, L0.z, L0.w);
                        mma_bf16(acc[m][2][0], acc[m][2][1], acc[m][2][2], acc[m][2][3],
                                 a0, a1, a2, a3, L1.x, L1.y);
                        mma_bf16(acc[m][3][0], acc[m][3][1], acc[m][3][2], acc[m][3][3],
                                 a0, a1, a2, a3, L1.z, L1.w);
                    }
                }
            }
        }
    }

    const int yOut = y0 + warpRow;
    #pragma unroll
    for (int m = 0; m < 4; m++) {
        #pragma unroll
        for (int hh = 0; hh < 2; hh++) {
            int px = pxBase + m*16 + groupId + hh*8;
            __nv_bfloat16* op = out + ((size_t)(bb*H + yOut)*W + x0 + px)*OSTR + outOff + quad*2;
            #pragma unroll
            for (int n = 0; n < 4; n++) {
                float v0 = acc[m][n][hh*2 + 0];
                float v1 = acc[m][n][hh*2 + 1];
                if (RELU) { v0 = fmaxf(v0, 0.f); v1 = fmaxf(v1, 0.f); }
                *(__nv_bfloat162*)(op + n*8) = __floats2bfloat162_rn(v0, v1);
            }
        }
    }
}

// =====================================================================
// shifted-window attention: 2 windows/block (128 thr), f32x2 packed math
// =====================================================================
__global__ __launch_bounds__(128)
void attn_k(const __nv_bfloat16* __restrict__ feat, const float* __restrict__ pos,
            __nv_bfloat16* __restrict__ aout)
{
    __shared__ float sK[2][64][32];
    __shared__ float sV[2][64][32];
    __shared__ float sPos[225];

    const int bb = blockIdx.y;
    const int tid = threadIdx.x;
    const int sub = tid >> 6;           // which window half
    const int t64 = tid & 63;
    const int w   = blockIdx.x*2 + sub;
    const int wh = w / NWIN, ww = w - wh*NWIN;
    const int iy = t64 >> 3, ix = t64 & 7;
    const int sy = wh*8 + iy, sx = ww*8 + ix;
    int y = sy + 4; if (y >= H) y -= H;
    int x = sx + 4; if (x >= W) x -= W;

    for (int idx = t64; idx < 64*4; idx += 64) {
        int j = idx >> 2, part = idx & 3;
        int jy = j >> 3, jx = j & 7;
        int yy = wh*8 + jy + 4; if (yy >= H) yy -= H;
        int xx = ww*8 + jx + 4; if (xx >= W) xx -= W;
        const __nv_bfloat16* p = feat + ((size_t)(bb*H + yy)*W + xx)*96;
        uint4 uk = *(const uint4*)(p + 32 + part*8);
        uint4 uv = *(const uint4*)(p + 64 + part*8);
        const __nv_bfloat162* hk = (const __nv_bfloat162*)&uk;
        const __nv_bfloat162* hv = (const __nv_bfloat162*)&uv;
        #pragma unroll
        for (int t = 0; t < 4; t++) {
            float2 fk = __bfloat1622float2(hk[t]);
            float2 fv = __bfloat1622float2(hv[t]);
            sK[sub][j][part*8 + t*2 + 0] = fk.x;
            sK[sub][j][part*8 + t*2 + 1] = fk.y;
            sV[sub][j][part*8 + t*2 + 0] = fv.x;
            sV[sub][j][part*8 + t*2 + 1] = fv.y;
        }
    }
    for (int idx = tid; idx < 225; idx += 128) sPos[idx] = pos[idx];

    unsigned long long q2[16];
    {
        const __nv_bfloat16* fp = feat + ((size_t)(bb*H + y)*W + x)*96;
        #pragma unroll
        for (int part = 0; part < 4; part++) {
            uint4 u = *(const uint4*)(fp + part*8);
            const __nv_bfloat162* hq = (const __nv_bfloat162*)&u;
            #pragma unroll
            for (int t = 0; t < 4; t++) {
                float2 f = __bfloat1622float2(hq[t]);
                q2[part*4 + t] = pack2(f.x, f.y);
            }
        }
    }
    __syncthreads();

    const bool mR = (wh == NWIN-1);
    const bool mC = (ww == NWIN-1);
    const float scale = 0.35355339059327373f;
    const int posOff = (7 - iy)*15 + (7 - ix);

    __nv_bfloat16* op = aout + ((size_t)(bb*H + sy)*W + sx)*32;

    #pragma unroll 1
    for (int h = 0; h < 4; h++) {
        float lg[64];
        float mx = -1e30f;
        #pragma unroll
        for (int j = 0; j < 64; j++) {
            const int jy = j >> 3, jx = j & 7;
            const unsigned long long* kp = (const unsigned long long*)&sK[sub][j][h*8];
            unsigned long long d2 = fma2(q2[h*4+0], kp[0], 0ULL);
            d2 = fma2(q2[h*4+1], kp[1], d2);
            d2 = fma2(q2[h*4+2], kp[2], d2);
            d2 = fma2(q2[h*4+3], kp[3], d2);
            float l = (lo2(d2) + hi2(d2))*scale + sPos[jy*15 + jx + posOff];
            bool msk = (mR && ((iy >= 4) != (jy >= 4))) ||
                       (mC && ((ix >= 4) != (jx >= 4)));
            l = msk ? -1e30f : l;
            lg[j] = l;
            mx = fmaxf(mx, l);
        }
        float s = 0.f;
        #pragma unroll
        for (int j = 0; j < 64; j++) {
            float e = __expf(lg[j] - mx);
            lg[j] = e;
            s += e;
        }
        const float inv = 1.f / s;
        unsigned long long oh2[4];
        #pragma unroll
        for (int d = 0; d < 4; d++) oh2[d] = 0ULL;
        #pragma unroll
        for (int j = 0; j < 64; j++) {
            unsigned long long pp = pack2(lg[j], lg[j]);
            const unsigned long long* vp = (const unsigned long long*)&sV[sub][j][h*8];
            oh2[0] = fma2(pp, vp[0], oh2[0]);
            oh2[1] = fma2(pp, vp[1], oh2[1]);
            oh2[2] = fma2(pp, vp[2], oh2[2]);
            oh2[3] = fma2(pp, vp[3], oh2[3]);
        }
        #pragma unroll
        for (int d = 0; d < 4; d++)
            *(__nv_bfloat162*)(op + h*8 + d*2) =
                __floats2bfloat162_rn(lo2(oh2[d])*inv, hi2(oh2[d])*inv);
    }
}

// =====================================================================
// conv_out GEMM (32->3, 8 couts padded) + roll(+4,+4) + residual, fp32 out
// =====================================================================
__global__ __launch_bounds__(256, 3)
void convout_gemm_k(const __nv_bfloat16* __restrict__ in, const uint32_t* __restrict__ gB,
                    const float* __restrict__ bias, const float* __restrict__ xin,
                    float* __restrict__ out)
{
    extern __shared__ __align__(16) char sAb[];

    const int bb = blockIdx.z;
    const int x0 = blockIdx.x * 128;
    const int y0 = blockIdx.y * 2;
    const int tid = threadIdx.x;
    const int warp = tid >> 5, lane = tid & 31;
    const int warpRow = warp >> 2;
    const int pxBase  = (warp & 3) * 32;
    const int groupId = lane >> 2, quad = lane & 3;

    const uint32_t aLane = smem_u32(sAb) + (uint32_t)((lane & 15)*(PADB*2) + (lane >> 4)*16);

    const int co0 = quad*2, co1 = quad*2 + 1;
    float acc[2][4];
    {
        float b0 = co0 < 3 ? __ldg(&bias[co0]) : 0.f;
        float b1 = co1 < 3 ? __ldg(&bias[co1]) : 0.f;
        #pragma unroll
        for (int m = 0; m < 2; m++) {
            acc[m][0] = b0; acc[m][1] = b1;
            acc[m][2] = b0; acc[m][3] = b1;
        }
    }

    #pragma unroll
    for (int r = 0; r < 4; r++) {
        int y = y0 - 1 + r;
        bool yin = (unsigned)y < (unsigned)H;
        for (int i = tid; i < 130*4; i += 256) {
            int px = i >> 2, v = i & 3;
            int x = x0 - 1 + px;
            bool inb = yin && ((unsigned)x < (unsigned)W);
            const __nv_bfloat16* src = in +
                ((size_t)(bb*H + (inb ? y : 0))*W + (inb ? x : 0))*32 + v*8;
            cp16(smem_u32(sAb + (size_t)(r*130 + px)*(PADB*2) + v*16), src, inb ? 16 : 0);
        }
    }
    cp_commit_wait();
    __syncthreads();

    #pragma unroll
    for (int dy = 0; dy < 3; dy++) {
        #pragma unroll
        for (int dx = 0; dx < 3; dx++) {
            const uint32_t aBase = aLane +
                (uint32_t)(((warpRow + dy)*130 + pxBase + dx)*(PADB*2));
            const uint2* pb2 = (const uint2*)gB + (dy*3 + dx)*2*32 + lane;
            #pragma unroll
            for (int kk = 0; kk < 2; kk++) {
                uint2 L = __ldg(pb2 + kk*32);
                #pragma unroll
                for (int m = 0; m < 2; m++) {
                    uint32_t a0, a1, a2, a3;
                    ldmA(a0, a1, a2, a3, aBase + (uint32_t)(m*16*(PADB*2) + kk*32));
                    mma_bf16(acc[m][0], acc[m][1], acc[m][2], acc[m][3],
                             a0, a1, a2, a3, L.x, L.y);
                }
            }
        }
    }

    const int gy = y0 + warpRow;
    int oy = gy + 4; if (oy >= H) oy -= H;
    #pragma unroll
    for (int m = 0; m < 2; m++) {
        #pragma unroll
        for (int hh = 0; hh < 2; hh++) {
            int gx = x0 + pxBase + m*16 + groupId + hh*8;
            int ox = gx + 4; if (ox >= W) ox -= W;
            if (co0 < 3) {
                size_t idx = ((size_t)(bb*3 + co0)*H + oy)*W + ox;
                out[idx] = xin[idx] + acc[m][hh*2 + 0];
            }
            if (co1 < 3) {
                size_t idx = ((size_t)(bb*3 + co1)*H + oy)*W + ox;
                out[idx] = xin[idx] + acc[m][hh*2 + 1];
            }
        }
    }
}

// ---------------- launcher ----------------
extern "C" void kernel_launch(void* const* d_in, const int* in_sizes, int n_in,
                              void* d_out, int out_size)
{
    (void)in_sizes; (void)n_in; (void)out_size;
    const float* x   = (const float*)d_in[0];
    const float* wo  = (const float*)d_in[19];
    const float* bo  = (const float*)d_in[20];
    const float* pos = (const float*)d_in[21];
    float* out = (float*)d_out;

    __nv_bfloat16 *h1, *h2, *feat, *aout;
    uint32_t *bf1, *bf2, *bf3, *bfo;
    cudaGetSymbolAddress((void**)&h1,   g_h1);
    cudaGetSymbolAddress((void**)&h2,   g_h2);
    cudaGetSymbolAddress((void**)&feat, g_feat);
    cudaGetSymbolAddress((void**)&aout, g_aout);
    cudaGetSymbolAddress((void**)&bf1,  g_bf1);
    cudaGetSymbolAddress((void**)&bf2,  g_bf2);
    cudaGetSymbolAddress((void**)&bf3,  g_bf3);
    cudaGetSymbolAddress((void**)&bfo,  g_bfo);

    // 6-row slabs exceed 48KB default dynamic smem limit
    cudaFuncSetAttribute((const void*)gemm_bf16_k<2,2,64,32,true,false>,
                         cudaFuncAttributeMaxDynamicSharedMemorySize, SMB4);
    cudaFuncSetAttribute((const void*)gemm_bf16_k<2,1,32,96,false,true>,
                         cudaFuncAttributeMaxDynamicSharedMemorySize, SMB4);

    // single merged B prep (45696 elements)
    prep_all_k<<<179, 256>>>(
        (const float*)d_in[1], (const float*)d_in[7],  (const float*)d_in[13],
        (const float*)d_in[3], (const float*)d_in[9],  (const float*)d_in[15],
        (const float*)d_in[5], (const float*)d_in[11], (const float*)d_in[17],
        wo, bf1, bf2, bf3, bfo);

    dim3 g1(W/128, H/2, BATCH);     // conv1 fused: z = bb
    dim3 gg(W/128, H/4, BATCH*3);   // conv2/conv3 4-row tiles: z = br*2 + bb

    conv1_im2col_k<<<g1, 256>>>(
        x, bf1,
        (const float*)d_in[2], (const float*)d_in[8], (const float*)d_in[14], h1);
    gemm_bf16_k<2, 2, 64, 32, true,  false><<<gg, 256, SMB4>>>(
        h1, bf2,
        (const float*)d_in[4], (const float*)d_in[10], (const float*)d_in[16],
        h2, H1SZ, H2SZ);
    gemm_bf16_k<2, 1, 32, 96, false, true ><<<gg, 256, SMB4>>>(
        h2, bf3,
        (const float*)d_in[6], (const float*)d_in[12], (const float*)d_in[18],
        feat, H2SZ, 0);

    attn_k<<<dim3(NWIN*NWIN/2, BATCH), 128>>>(feat, pos, aout);
    convout_gemm_k<<<g1, 256, SMB>>>(aout, bfo, bo, x, out);
}

// round 17
// speedup vs baseline: 1.0918x; 1.0360x over previous
#include <cuda_runtime.h>
#include <cuda_bf16.h>
#include <cstdint>
#include <cstddef>

#define H 384
#define W 384
#define BATCH 2
#define NWIN 48

#define H1SZ ((size_t)BATCH*H*W*64)   // elements per branch (bf16)
#define H2SZ ((size_t)BATCH*H*W*32)

// ---------------- scratch ----------------
__device__ __nv_bfloat16 g_h1[3*H1SZ];
__device__ __nv_bfloat16 g_h2[3*H2SZ];
__device__ __nv_bfloat16 g_feat[(size_t)BATCH*H*W*96];
__device__ __nv_bfloat16 g_aout[(size_t)BATCH*H*W*32];   // channel-last, shifted space
__device__ uint32_t g_bf1[3*1024];     // conv1 B frags (bf16x2, im2col K=32)
__device__ uint32_t g_bf2[3*9216];     // conv2 B frags (KSTEPS=4 layout)
__device__ uint32_t g_bf3[3*4608];     // conv3 B frags (KSTEPS=2 layout)
__device__ uint32_t g_bfo[1152];       // conv_out B frags (8 couts, 3 real)

// ---------------- helpers ----------------
__device__ __forceinline__ void mma_bf16(float& c0, float& c1, float& c2, float& c3,
                                         uint32_t a0, uint32_t a1, uint32_t a2, uint32_t a3,
                                         uint32_t b0, uint32_t b1) {
    asm volatile("mma.sync.aligned.m16n8k16.row.col.f32.bf16.bf16.f32 "
                 "{%0,%1,%2,%3}, {%4,%5,%6,%7}, {%8,%9}, {%0,%1,%2,%3};"
                 : "+f"(c0), "+f"(c1), "+f"(c2), "+f"(c3)
                 : "r"(a0), "r"(a1), "r"(a2), "r"(a3), "r"(b0), "r"(b1));
}
__device__ __forceinline__ void ldmA(uint32_t& r0, uint32_t& r1, uint32_t& r2, uint32_t& r3,
                                     uint32_t addr) {
    asm volatile("ldmatrix.sync.aligned.m8n8.x4.shared.b16 {%0,%1,%2,%3}, [%4];"
                 : "=r"(r0), "=r"(r1), "=r"(r2), "=r"(r3) : "r"(addr));
}
__device__ __forceinline__ uint32_t smem_u32(const void* p) {
    return (uint32_t)__cvta_generic_to_shared(p);
}
__device__ __forceinline__ void cp16(uint32_t dst, const void* src, int sz) {
    asm volatile("cp.async.cg.shared.global [%0], [%1], 16, %2;"
                 :: "r"(dst), "l"(src), "r"(sz));
}
__device__ __forceinline__ void cp_commit_wait() {
    asm volatile("cp.async.commit_group;");
    asm volatile("cp.async.wait_group 0;");
}
// packed fp32x2
__device__ __forceinline__ unsigned long long pack2(float lo, float hi) {
    unsigned long long r;
    asm("mov.b64 %0, {%1, %2};" : "=l"(r) : "f"(lo), "f"(hi));
    return r;
}
__device__ __forceinline__ unsigned long long fma2(unsigned long long a,
                                                   unsigned long long b,
                                                   unsigned long long c) {
    unsigned long long d;
    asm("fma.rn.f32x2 %0, %1, %2, %3;" : "=l"(d) : "l"(a), "l"(b), "l"(c));
    return d;
}
__device__ __forceinline__ float lo2(unsigned long long v) {
    return __uint_as_float((unsigned)(v & 0xffffffffULL));
}
__device__ __forceinline__ float hi2(unsigned long long v) {
    return __uint_as_float((unsigned)(v >> 32));
}

// =====================================================================
// merged B prep: bf1 (3x1024) | bf2 (3x9216, KSTEPS=4) | bf3 (3x4608) | bfo (1152)
// =====================================================================
__global__ void prep_all_k(const float* __restrict__ w1a, const float* __restrict__ w1b,
                           const float* __restrict__ w1c,
                           const float* __restrict__ w2a, const float* __restrict__ w2b,
                           const float* __restrict__ w2c,
                           const float* __restrict__ w3a, const float* __restrict__ w3b,
                           const float* __restrict__ w3c,
                           const float* __restrict__ wo,
                           uint32_t* __restrict__ bf1, uint32_t* __restrict__ bf2,
                           uint32_t* __restrict__ bf3, uint32_t* __restrict__ bfo)
{
    int gid = blockIdx.x*256 + threadIdx.x;

    if (gid < 3072) {                                   // conv1: im2col K=32 (27 real)
        int br = gid / 1024, idx = gid - br*1024;
        const float* wt = br == 0 ? w1a : (br == 1 ? w1b : w1c);
        int r    = idx & 3;
        int lane = (idx >> 2) & 31;
        int half = (idx >> 7) & 3;
        int kk   = idx >> 9;
        int n    = half*2 + (r >> 1);
        int breg = r & 1;
        int k0 = kk*16 + (lane & 3)*2 + breg*8;
        int co = n*8 + (lane >> 2);
        float v0 = 0.f, v1 = 0.f;
        if (k0 + 0 < 27) v0 = wt[(co*3 + (k0+0)/9)*9 + (k0+0)%9];
        if (k0 + 1 < 27) v1 = wt[(co*3 + (k0+1)/9)*9 + (k0+1)%9];
        __nv_bfloat162 pk = __floats2bfloat162_rn(v0, v1);
        bf1[gid] = *(uint32_t*)&pk;
        return;
    }
    gid -= 3072;
    if (gid < 27648) {                                  // conv2: CIN=64, KSTEPS=4 NCHUNK=1
        int br = gid / 9216, idx = gid - br*9216;
        const float* wt = br == 0 ? w2a : (br == 1 ? w2b : w2c);
        int r    = idx & 3;
        int lane = (idx >> 2) & 31;
        int half = (idx >> 7) & 1;
        int rest = idx >> 8;
        int kk   = rest & 3;
        int dydx = rest >> 2;
        int n    = half*2 + (r >> 1);
        int breg = r & 1;
        int ci = kk*16 + (lane & 3)*2 + breg*8;
        int co = n*8 + (lane >> 2);
        __nv_bfloat162 pk = __floats2bfloat162_rn(
            wt[(co*64 + ci + 0)*9 + dydx], wt[(co*64 + ci + 1)*9 + dydx]);
        bf2[br*9216 + idx] = *(uint32_t*)&pk;
        return;
    }
    gid -= 27648;
    if (gid < 13824) {                                  // conv3: CIN=32, KSTEPS=2
        int br = gid / 4608, idx = gid - br*4608;
        const float* wt = br == 0 ? w3a : (br == 1 ? w3b : w3c);
        int r    = idx & 3;
        int lane = (idx >> 2) & 31;
        int half = (idx >> 7) & 1;
        int rest = idx >> 8;
        int kk   = rest & 1;
        int dydx = rest >> 1;
        int n    = half*2 + (r >> 1);
        int breg = r & 1;
        int ci = kk*16 + (lane & 3)*2 + breg*8;
        int co = n*8 + (lane >> 2);
        __nv_bfloat162 pk = __floats2bfloat162_rn(
            wt[(co*32 + ci + 0)*9 + dydx], wt[(co*32 + ci + 1)*9 + dydx]);
        bf3[br*4608 + idx] = *(uint32_t*)&pk;
        return;
    }
    gid -= 13824;
    if (gid < 1152) {                                   // conv_out: 8 couts (3 real)
        int idx = gid;
        int breg = idx & 1;
        int lane = (idx >> 1) & 31;
        int kk   = (idx >> 6) & 1;
        int dydx = idx >> 7;
        int ci = kk*16 + (lane & 3)*2 + breg*8;
        int co = lane >> 2;
        float v0 = 0.f, v1 = 0.f;
        if (co < 3) {
            v0 = wo[(co*32 + ci + 0)*9 + dydx];
            v1 = wo[(co*32 + ci + 1)*9 + dydx];
        }
        __nv_bfloat162 pk = __floats2bfloat162_rn(v0, v1);
        bfo[idx] = *(uint32_t*)&pk;
    }
}

// =====================================================================
// conv1 fused: 3->64 x 3 branches. Vectorized fill, hoisted A-fragments.
// =====================================================================
#define PADB 40

__global__ __launch_bounds__(256, 2)
void conv1_im2col_k(const float* __restrict__ in, const uint32_t* __restrict__ gB,
                    const float* __restrict__ bias0, const float* __restrict__ bias1,
                    const float* __restrict__ bias2, __nv_bfloat16* __restrict__ out)
{
    __shared__ __align__(16) float sRaw[3][4][136];   // xx=0 <-> global x0-4
    __shared__ __align__(16) __nv_bfloat16 sA[256][PADB];

    const int bb = blockIdx.z;
    const int x0 = blockIdx.x * 128;
    const int y0 = blockIdx.y * 2;
    const int tid = threadIdx.x;
    const int warp = tid >> 5, lane = tid & 31;
    const int warpRow = warp >> 2;
    const int pxBase  = (warp & 3) * 32;
    const int groupId = lane >> 2, quad = lane & 3;

    for (int i = tid; i < 3*4*33; i += 256) {
        int ci = i / 132;
        int r2 = i - ci*132;
        int rr = r2 / 33;
        int g  = r2 - rr*33;
        int y  = y0 - 1 + rr;
        int xg = x0 - 4 + g*4;
        bool inb = ((unsigned)y < (unsigned)H) && (xg >= 0);
        const float* src = in + ((size_t)(bb*3 + ci)*H + (inb ? y : 0))*W + (inb ? xg : 0);
        cp16(smem_u32(&sRaw[ci][rr][g*4]), src, inb ? 16 : 0);
    }
    cp_commit_wait();
    __syncthreads();

    {
        int r = tid >> 7, px = tid & 127;
        float vals[32];
        #pragma unroll
        for (int ci = 0; ci < 3; ci++)
            #pragma unroll
            for (int dy = 0; dy < 3; dy++)
                #pragma unroll
                for (int dx = 0; dx < 3; dx++)
                    vals[ci*9 + dy*3 + dx] = sRaw[ci][r + dy][px + 3 + dx];
        #pragma unroll
        for (int k = 27; k < 32; k++) vals[k] = 0.f;
        uint32_t pk[16];
        #pragma unroll
        for (int t = 0; t < 16; t++) {
            __nv_bfloat162 p = __floats2bfloat162_rn(vals[2*t], vals[2*t+1]);
            pk[t] = *(uint32_t*)&p;
        }
        uint4* dstp = (uint4*)&sA[tid][0];
        dstp[0] = make_uint4(pk[0],  pk[1],  pk[2],  pk[3]);
        dstp[1] = make_uint4(pk[4],  pk[5],  pk[6],  pk[7]);
        dstp[2] = make_uint4(pk[8],  pk[9],  pk[10], pk[11]);
        dstp[3] = make_uint4(pk[12], pk[13], pk[14], pk[15]);
    }
    __syncthreads();

    const uint32_t aLane = smem_u32(sA) +
        (uint32_t)((warpRow*128 + pxBase + (lane & 15))*(PADB*2) + (lane >> 4)*16);
    const int yOut = y0 + warpRow;

    uint32_t afr[2][2][4];
    #pragma unroll
    for (int kk = 0; kk < 2; kk++)
        #pragma unroll
        for (int m = 0; m < 2; m++)
            ldmA(afr[kk][m][0], afr[kk][m][1], afr[kk][m][2], afr[kk][m][3],
                 aLane + (uint32_t)(m*16*(PADB*2) + kk*32));

    #pragma unroll 1
    for (int br = 0; br < 3; br++) {
        const float* bias = br == 0 ? bias0 : (br == 1 ? bias1 : bias2);
        const uint4* pb4 = (const uint4*)(gB + br*1024) + lane;
        __nv_bfloat16* outp = out + (size_t)br * H1SZ;

        float acc[2][8][4];
        #pragma unroll
        for (int n = 0; n < 8; n++) {
            float b0 = __ldg(&bias[n*8 + quad*2 + 0]);
            float b1 = __ldg(&bias[n*8 + quad*2 + 1]);
            #pragma unroll
            for (int m = 0; m < 2; m++) {
                acc[m][n][0] = b0; acc[m][n][1] = b1;
                acc[m][n][2] = b0; acc[m][n][3] = b1;
            }
        }

        #pragma unroll
        for (int kk = 0; kk < 2; kk++) {
            uint4 L0 = __ldg(pb4 + kk*128);
            uint4 L1 = __ldg(pb4 + kk*128 + 32);
            uint4 L2 = __ldg(pb4 + kk*128 + 64);
            uint4 L3 = __ldg(pb4 + kk*128 + 96);
            #pragma unroll
            for (int m = 0; m < 2; m++) {
                uint32_t a0 = afr[kk][m][0], a1 = afr[kk][m][1];
                uint32_t a2 = afr[kk][m][2], a3 = afr[kk][m][3];
                mma_bf16(acc[m][0][0], acc[m][0][1], acc[m][0][2], acc[m][0][3], a0,a1,a2,a3, L0.x, L0.y);
                mma_bf16(acc[m][1][0], acc[m][1][1], acc[m][1][2], acc[m][1][3], a0,a1,a2,a3, L0.z, L0.w);
                mma_bf16(acc[m][2][0], acc[m][2][1], acc[m][2][2], acc[m][2][3], a0,a1,a2,a3, L1.x, L1.y);
                mma_bf16(acc[m][3][0], acc[m][3][1], acc[m][3][2], acc[m][3][3], a0,a1,a2,a3, L1.z, L1.w);
                mma_bf16(acc[m][4][0], acc[m][4][1], acc[m][4][2], acc[m][4][3], a0,a1,a2,a3, L2.x, L2.y);
                mma_bf16(acc[m][5][0], acc[m][5][1], acc[m][5][2], acc[m][5][3], a0,a1,a2,a3, L2.z, L2.w);
                mma_bf16(acc[m][6][0], acc[m][6][1], acc[m][6][2], acc[m][6][3], a0,a1,a2,a3, L3.x, L3.y);
                mma_bf16(acc[m][7][0], acc[m][7][1], acc[m][7][2], acc[m][7][3], a0,a1,a2,a3, L3.z, L3.w);
            }
        }

        #pragma unroll
        for (int m = 0; m < 2; m++) {
            #pragma unroll
            for (int hh = 0; hh < 2; hh++) {
                int px = pxBase + m*16 + groupId + hh*8;
                __nv_bfloat16* op = outp + ((size_t)(bb*H + yOut)*W + x0 + px)*64 + quad*2;
                #pragma unroll
                for (int n = 0; n < 8; n++) {
                    float v0 = fmaxf(acc[m][n][hh*2 + 0], 0.f);
                    float v1 = fmaxf(acc[m][n][hh*2 + 1], 0.f);
                    *(__nv_bfloat162*)(op + n*8) = __floats2bfloat162_rn(v0, v1);
                }
            }
        }
    }
}

// =====================================================================
// bf16 implicit-GEMM conv: 4 rows x 128 px per block, z = br*2 + bb.
// CHK channels per slab pass, PADX bf16 px stride, KSTEPS k-steps/tap.
// =====================================================================
#define SMB2 (6*130*72*2)
#define SMB3 (6*130*40*2)

template<int CHK, int PADX, int KSTEPS, int NCHUNK, int CINTOT, int OSTR, bool RELU, bool FEAT>
__global__ __launch_bounds__(256, 2)
void gemm_bf16_k(const __nv_bfloat16* __restrict__ in, const uint32_t* __restrict__ gB,
                 const float* __restrict__ bias0, const float* __restrict__ bias1,
                 const float* __restrict__ bias2, __nv_bfloat16* __restrict__ out,
                 size_t inStride, size_t outStride)
{
    extern __shared__ __align__(16) char sAb[];
    constexpr int BSZ = NCHUNK*9*KSTEPS*256;
    constexpr int VPP = CHK/8;   // uint4 per pixel

    const int z  = blockIdx.z;
    const int bb = z & 1;
    const int br = z >> 1;
    const float* bias = br == 0 ? bias0 : (br == 1 ? bias1 : bias2);
    in  += (size_t)br * inStride;
    out += (size_t)br * outStride;
    gB  += br * BSZ;
    const int outOff = FEAT ? br*32 : 0;

    const int x0 = blockIdx.x * 128;
    const int y0 = blockIdx.y * 4;
    const int tid = threadIdx.x;
    const int warp = tid >> 5, lane = tid & 31;
    const int warpRow = warp >> 1;          // 0..3
    const int pxBase  = (warp & 1) * 64;    // 0 or 64
    const int groupId = lane >> 2, quad = lane & 3;

    const uint32_t aLane = smem_u32(sAb) + (uint32_t)((lane & 15)*(PADX*2) + (lane >> 4)*16);

    float acc[4][4][4];
    #pragma unroll
    for (int n = 0; n < 4; n++) {
        float b0 = __ldg(&bias[n*8 + quad*2 + 0]);
        float b1 = __ldg(&bias[n*8 + quad*2 + 1]);
        #pragma unroll
        for (int m = 0; m < 4; m++) {
            acc[m][n][0] = b0; acc[m][n][1] = b1;
            acc[m][n][2] = b0; acc[m][n][3] = b1;
        }
    }

    #pragma unroll 1
    for (int ch = 0; ch < NCHUNK; ch++) {
        __syncthreads();
        #pragma unroll
        for (int r = 0; r < 6; r++) {
            int y = y0 - 1 + r;
            bool yin = (unsigned)y < (unsigned)H;
            for (int i = tid; i < 130*VPP; i += 256) {
                int px = i / VPP, v = i - px*VPP;
                int x = x0 - 1 + px;
                bool inb = yin && ((unsigned)x < (unsigned)W);
                const __nv_bfloat16* src = in +
                    ((size_t)(bb*H + (inb ? y : 0))*W + (inb ? x : 0))*CINTOT + ch*CHK + v*8;
                cp16(smem_u32(sAb + (size_t)(r*130 + px)*(PADX*2) + v*16), src, inb ? 16 : 0);
            }
        }
        cp_commit_wait();
        __syncthreads();

        #pragma unroll
        for (int dy = 0; dy < 3; dy++) {
            #pragma unroll
            for (int dx = 0; dx < 3; dx++) {
                const uint32_t aBase = aLane +
                    (uint32_t)(((warpRow + dy)*130 + pxBase + dx)*(PADX*2));
                const uint4* pb4 = (const uint4*)gB + ((ch*9 + dy*3 + dx)*KSTEPS)*64 + lane;
                #pragma unroll
                for (int kk = 0; kk < KSTEPS; kk++) {
                    uint4 L0 = __ldg(pb4 + kk*64);
                    uint4 L1 = __ldg(pb4 + kk*64 + 32);
                    #pragma unroll
                    for (int m = 0; m < 4; m++) {
                        uint32_t a0, a1, a2, a3;
                        ldmA(a0, a1, a2, a3, aBase + (uint32_t)(m*16*(PADX*2) + kk*32));
                        mma_bf16(acc[m][0][0], acc[m][0][1], acc[m][0][2], acc[m][0][3],
                                 a0, a1, a2, a3, L0.x, L0.y);
                        mma_bf16(acc[m][1][0], acc[m][1][1], acc[m][1][2], acc[m][1][3],
                                 a0, a1, a2, a3, L0.z, L0.w);
                        mma_bf16(acc[m][2][0], acc[m][2][1], acc[m][2][2], acc[m][2][3],
                                 a0, a1, a2, a3, L1.x, L1.y);
                        mma_bf16(acc[m][3][0], acc[m][3][1], acc[m][3][2], acc[m][3][3],
                                 a0, a1, a2, a3, L1.z, L1.w);
                    }
                }
            }
        }
    }

    const int yOut = y0 + warpRow;
    #pragma unroll
    for (int m = 0; m < 4; m++) {
        #pragma unroll
        for (int hh = 0; hh < 2; hh++) {
            int px = pxBase + m*16 + groupId + hh*8;
            __nv_bfloat16* op = out + ((size_t)(bb*H + yOut)*W + x0 + px)*OSTR + outOff + quad*2;
            #pragma unroll
            for (int n = 0; n < 4; n++) {
                float v0 = acc[m][n][hh*2 + 0];
                float v1 = acc[m][n][hh*2 + 1];
                if (RELU) { v0 = fmaxf(v0, 0.f); v1 = fmaxf(v1, 0.f); }
                *(__nv_bfloat162*)(op + n*8) = __floats2bfloat162_rn(v0, v1);
            }
        }
    }
}

// =====================================================================
// shifted-window attention: 2 windows/block (128 thr), f32x2 packed math
// =====================================================================
__global__ __launch_bounds__(128)
void attn_k(const __nv_bfloat16* __restrict__ feat, const float* __restrict__ pos,
            __nv_bfloat16* __restrict__ aout)
{
    __shared__ float sK[2][64][32];
    __shared__ float sV[2][64][32];
    __shared__ float sPos[225];

    const int bb = blockIdx.y;
    const int tid = threadIdx.x;
    const int sub = tid >> 6;
    const int t64 = tid & 63;
    const int w   = blockIdx.x*2 + sub;
    const int wh = w / NWIN, ww = w - wh*NWIN;
    const int iy = t64 >> 3, ix = t64 & 7;
    const int sy = wh*8 + iy, sx = ww*8 + ix;
    int y = sy + 4; if (y >= H) y -= H;
    int x = sx + 4; if (x >= W) x -= W;

    for (int idx = t64; idx < 64*4; idx += 64) {
        int j = idx >> 2, part = idx & 3;
        int jy = j >> 3, jx = j & 7;
        int yy = wh*8 + jy + 4; if (yy >= H) yy -= H;
        int xx = ww*8 + jx + 4; if (xx >= W) xx -= W;
        const __nv_bfloat16* p = feat + ((size_t)(bb*H + yy)*W + xx)*96;
        uint4 uk = *(const uint4*)(p + 32 + part*8);
        uint4 uv = *(const uint4*)(p + 64 + part*8);
        const __nv_bfloat162* hk = (const __nv_bfloat162*)&uk;
        const __nv_bfloat162* hv = (const __nv_bfloat162*)&uv;
        #pragma unroll
        for (int t = 0; t < 4; t++) {
            float2 fk = __bfloat1622float2(hk[t]);
            float2 fv = __bfloat1622float2(hv[t]);
            sK[sub][j][part*8 + t*2 + 0] = fk.x;
            sK[sub][j][part*8 + t*2 + 1] = fk.y;
            sV[sub][j][part*8 + t*2 + 0] = fv.x;
            sV[sub][j][part*8 + t*2 + 1] = fv.y;
        }
    }
    for (int idx = tid; idx < 225; idx += 128) sPos[idx] = pos[idx];

    unsigned long long q2[16];
    {
        const __nv_bfloat16* fp = feat + ((size_t)(bb*H + y)*W + x)*96;
        #pragma unroll
        for (int part = 0; part < 4; part++) {
            uint4 u = *(const uint4*)(fp + part*8);
            const __nv_bfloat162* hq = (const __nv_bfloat162*)&u;
            #pragma unroll
            for (int t = 0; t < 4; t++) {
                float2 f = __bfloat1622float2(hq[t]);
                q2[part*4 + t] = pack2(f.x, f.y);
            }
        }
    }
    __syncthreads();

    const bool mR = (wh == NWIN-1);
    const bool mC = (ww == NWIN-1);
    const float scale = 0.35355339059327373f;
    const int posOff = (7 - iy)*15 + (7 - ix);

    __nv_bfloat16* op = aout + ((size_t)(bb*H + sy)*W + sx)*32;

    #pragma unroll 1
    for (int h = 0; h < 4; h++) {
        float lg[64];
        float mx = -1e30f;
        #pragma unroll
        for (int j = 0; j < 64; j++) {
            const int jy = j >> 3, jx = j & 7;
            const unsigned long long* kp = (const unsigned long long*)&sK[sub][j][h*8];
            unsigned long long d2 = fma2(q2[h*4+0], kp[0], 0ULL);
            d2 = fma2(q2[h*4+1], kp[1], d2);
            d2 = fma2(q2[h*4+2], kp[2], d2);
            d2 = fma2(q2[h*4+3], kp[3], d2);
            float l = (lo2(d2) + hi2(d2))*scale + sPos[jy*15 + jx + posOff];
            bool msk = (mR && ((iy >= 4) != (jy >= 4))) ||
                       (mC && ((ix >= 4) != (jx >= 4)));
            l = msk ? -1e30f : l;
            lg[j] = l;
            mx = fmaxf(mx, l);
        }
        float s = 0.f;
        #pragma unroll
        for (int j = 0; j < 64; j++) {
            float e = __expf(lg[j] - mx);
            lg[j] = e;
            s += e;
        }
        const float inv = 1.f / s;
        unsigned long long oh2[4];
        #pragma unroll
        for (int d = 0; d < 4; d++) oh2[d] = 0ULL;
        #pragma unroll
        for (int j = 0; j < 64; j++) {
            unsigned long long pp = pack2(lg[j], lg[j]);
            const unsigned long long* vp = (const unsigned long long*)&sV[sub][j][h*8];
            oh2[0] = fma2(pp, vp[0], oh2[0]);
            oh2[1] = fma2(pp, vp[1], oh2[1]);
            oh2[2] = fma2(pp, vp[2], oh2[2]);
            oh2[3] = fma2(pp, vp[3], oh2[3]);
        }
        #pragma unroll
        for (int d = 0; d < 4; d++)
            *(__nv_bfloat162*)(op + h*8 + d*2) =
                __floats2bfloat162_rn(lo2(oh2[d])*inv, hi2(oh2[d])*inv);
    }
}

// =====================================================================
// conv_out GEMM (32->3, 8 couts padded): 4-row tile + roll + residual
// =====================================================================
__global__ __launch_bounds__(256, 2)
void convout_gemm_k(const __nv_bfloat16* __restrict__ in, const uint32_t* __restrict__ gB,
                    const float* __restrict__ bias, const float* __restrict__ xin,
                    float* __restrict__ out)
{
    extern __shared__ __align__(16) char sAb[];

    const int bb = blockIdx.z;
    const int x0 = blockIdx.x * 128;
    const int y0 = blockIdx.y * 4;
    const int tid = threadIdx.x;
    const int warp = tid >> 5, lane = tid & 31;
    const int warpRow = warp >> 1;          // 0..3
    const int pxBase  = (warp & 1) * 64;    // 0 or 64
    const int groupId = lane >> 2, quad = lane & 3;

    const uint32_t aLane = smem_u32(sAb) + (uint32_t)((lane & 15)*(PADB*2) + (lane >> 4)*16);

    const int co0 = quad*2, co1 = quad*2 + 1;
    float acc[4][4];
    {
        float b0 = co0 < 3 ? __ldg(&bias[co0]) : 0.f;
        float b1 = co1 < 3 ? __ldg(&bias[co1]) : 0.f;
        #pragma unroll
        for (int m = 0; m < 4; m++) {
            acc[m][0] = b0; acc[m][1] = b1;
            acc[m][2] = b0; acc[m][3] = b1;
        }
    }

    #pragma unroll
    for (int r = 0; r < 6; r++) {
        int y = y0 - 1 + r;
        bool yin = (unsigned)y < (unsigned)H;
        for (int i = tid; i < 130*4; i += 256) {
            int px = i >> 2, v = i & 3;
            int x = x0 - 1 + px;
            bool inb = yin && ((unsigned)x < (unsigned)W);
            const __nv_bfloat16* src = in +
                ((size_t)(bb*H + (inb ? y : 0))*W + (inb ? x : 0))*32 + v*8;
            cp16(smem_u32(sAb + (size_t)(r*130 + px)*(PADB*2) + v*16), src, inb ? 16 : 0);
        }
    }
    cp_commit_wait();
    __syncthreads();

    #pragma unroll
    for (int dy = 0; dy < 3; dy++) {
        #pragma unroll
        for (int dx = 0; dx < 3; dx++) {
            const uint32_t aBase = aLane +
                (uint32_t)(((warpRow + dy)*130 + pxBase + dx)*(PADB*2));
            const uint2* pb2 = (const uint2*)gB + (dy*3 + dx)*2*32 + lane;
            #pragma unroll
            for (int kk = 0; kk < 2; kk++) {
                uint2 L = __ldg(pb2 + kk*32);
                #pragma unroll
                for (int m = 0; m < 4; m++) {
                    uint32_t a0, a1, a2, a3;
                    ldmA(a0, a1, a2, a3, aBase + (uint32_t)(m*16*(PADB*2) + kk*32));
                    mma_bf16(acc[m][0], acc[m][1], acc[m][2], acc[m][3],
                             a0, a1, a2, a3, L.x, L.y);
                }
            }
        }
    }

    const int gy = y0 + warpRow;
    int oy = gy + 4; if (oy >= H) oy -= H;
    #pragma unroll
    for (int m = 0; m < 4; m++) {
        #pragma unroll
        for (int hh = 0; hh < 2; hh++) {
            int gx = x0 + pxBase + m*16 + groupId + hh*8;
            int ox = gx + 4; if (ox >= W) ox -= W;
            if (co0 < 3) {
                size_t idx = ((size_t)(bb*3 + co0)*H + oy)*W + ox;
                out[idx] = xin[idx] + acc[m][hh*2 + 0];
            }
            if (co1 < 3) {
                size_t idx = ((size_t)(bb*3 + co1)*H + oy)*W + ox;
                out[idx] = xin[idx] + acc[m][hh*2 + 1];
            }
        }
    }
}

// ---------------- launcher ----------------
extern "C" void kernel_launch(void* const* d_in, const int* in_sizes, int n_in,
                              void* d_out, int out_size)
{
    (void)in_sizes; (void)n_in; (void)out_size;
    const float* x   = (const float*)d_in[0];
    const float* wo  = (const float*)d_in[19];
    const float* bo  = (const float*)d_in[20];
    const float* pos = (const float*)d_in[21];
    float* out = (float*)d_out;

    __nv_bfloat16 *h1, *h2, *feat, *aout;
    uint32_t *bf1, *bf2, *bf3, *bfo;
    cudaGetSymbolAddress((void**)&h1,   g_h1);
    cudaGetSymbolAddress((void**)&h2,   g_h2);
    cudaGetSymbolAddress((void**)&feat, g_feat);
    cudaGetSymbolAddress((void**)&aout, g_aout);
    cudaGetSymbolAddress((void**)&bf1,  g_bf1);
    cudaGetSymbolAddress((void**)&bf2,  g_bf2);
    cudaGetSymbolAddress((void**)&bf3,  g_bf3);
    cudaGetSymbolAddress((void**)&bfo,  g_bfo);

    cudaFuncSetAttribute((const void*)gemm_bf16_k<64,72,4,1,64,32,true,false>,
                         cudaFuncAttributeMaxDynamicSharedMemorySize, SMB2);
    cudaFuncSetAttribute((const void*)gemm_bf16_k<32,40,2,1,32,96,false,true>,
                         cudaFuncAttributeMaxDynamicSharedMemorySize, SMB3);
    cudaFuncSetAttribute((const void*)convout_gemm_k,
                         cudaFuncAttributeMaxDynamicSharedMemorySize, SMB3);

    prep_all_k<<<179, 256>>>(
        (const float*)d_in[1], (const float*)d_in[7],  (const float*)d_in[13],
        (const float*)d_in[3], (const float*)d_in[9],  (const float*)d_in[15],
        (const float*)d_in[5], (const float*)d_in[11], (const float*)d_in[17],
        wo, bf1, bf2, bf3, bfo);

    dim3 g1(W/128, H/2, BATCH);     // conv1 fused: z = bb
    dim3 gg(W/128, H/4, BATCH*3);   // conv2/conv3 4-row tiles: z = br*2 + bb
    dim3 go(W/128, H/4, BATCH);     // convout 4-row tiles

    conv1_im2col_k<<<g1, 256>>>(
        x, bf1,
        (const float*)d_in[2], (const float*)d_in[8], (const float*)d_in[14], h1);
    gemm_bf16_k<64,72,4,1,64,32,true, false><<<gg, 256, SMB2>>>(
        h1, bf2,
        (const float*)d_in[4], (const float*)d_in[10], (const float*)d_in[16],
        h2, H1SZ, H2SZ);
    gemm_bf16_k<32,40,2,1,32,96,false,true ><<<gg, 256, SMB3>>>(
        h2, bf3,
        (const float*)d_in[6], (const float*)d_in[12], (const float*)d_in[18],
        feat, H2SZ, 0);

    attn_k<<<dim3(NWIN*NWIN/2, BATCH), 128>>>(feat, pos, aout);
    convout_gemm_k<<<go, 256, SMB3>>>(aout, bfo, bo, x, out);
}